// round 3
// baseline (speedup 1.0000x reference)
#include <cuda_runtime.h>
#include <cstdint>
#include <math.h>

#define MTOT 4096
#define DIN  4096
#define DOUT 4096
#define KEXT 128
#define KCAT 4224          // DIN + KEXT
#define NSTAGE 3
#define STAGE_BYTES 32768  // 16KB A + 16KB W
#define SMEM_SZ (NSTAGE*STAGE_BYTES + 1024)
#define NSPLIT 8

// ---------------- static device scratch ----------------
__device__ float g_A[(size_t)MTOT * KCAT];     // [x | ext], tf32-rounded
__device__ float g_W[(size_t)DOUT * KCAT];     // [base_w | lora_B flat], tf32-rounded
__device__ float g_LA[(size_t)KEXT * DIN];     // lora_A rows, tf32-rounded
__device__ float g_lowp[(size_t)NSPLIT * MTOT * KEXT]; // split-K partials of x @ lora_A^T
__device__ float g_coef[(size_t)MTOT * 8];     // scaling * routing weight (dense)

// ---------------- helpers ----------------
__device__ __forceinline__ uint32_t smem_u32(const void* p) {
    uint32_t a;
    asm("{ .reg .u64 t; cvta.to.shared.u64 t, %1; cvt.u32.u64 %0, t; }" : "=r"(a) : "l"(p));
    return a;
}
__device__ __forceinline__ uint32_t sw128(uint32_t o) { return o ^ ((o >> 3) & 0x70); }
__device__ __forceinline__ void cp16(uint32_t dst, const void* src) {
    asm volatile("cp.async.cg.shared.global [%0], [%1], 16;" :: "r"(dst), "l"(src) : "memory");
}
__device__ __forceinline__ void cp_commit() {
    asm volatile("cp.async.commit_group;" ::: "memory");
}
__device__ __forceinline__ float tf32r(float v) {
    uint32_t r; asm("cvt.rna.tf32.f32 %0, %1;" : "=r"(r) : "f"(v));
    return __uint_as_float(r);
}
__device__ __forceinline__ void ldsm4(uint32_t* r, uint32_t addr) {
    asm volatile("ldmatrix.sync.aligned.m8n8.x4.shared.b16 {%0,%1,%2,%3}, [%4];"
                 : "=r"(r[0]), "=r"(r[1]), "=r"(r[2]), "=r"(r[3]) : "r"(addr));
}
__device__ __forceinline__ void mma168(float* d, const uint32_t* a, uint32_t b0, uint32_t b1) {
    asm volatile("mma.sync.aligned.m16n8k8.row.col.f32.tf32.tf32.f32 "
                 "{%0,%1,%2,%3}, {%4,%5,%6,%7}, {%8,%9}, {%0,%1,%2,%3};"
                 : "+f"(d[0]), "+f"(d[1]), "+f"(d[2]), "+f"(d[3])
                 : "r"(a[0]), "r"(a[1]), "r"(a[2]), "r"(a[3]), "r"(b0), "r"(b1));
}

// ---------------- tf32 GEMM: out[M x N] = A[M x kLen] * W[N x kLen]^T (+bias) ----------------
// CTA tile 128x128, 256 threads (warp tile 64x32), K chunk 32, 3-stage cp.async pipeline.
// Split-K via blockIdx.z: reads cols [z*kLen, (z+1)*kLen), writes out + z*splitStride.
__global__ void __launch_bounds__(256, 2) gemm_tf32(
    const float* __restrict__ A, int lda, int kLen,
    const float* __restrict__ W, int ldw,
    float* __restrict__ out, int ldo,
    const float* __restrict__ bias, long splitStride)
{
    extern __shared__ char dyn[];
    uint32_t smem = (smem_u32(dyn) + 1023u) & ~1023u;

    int tid = threadIdx.x, lane = tid & 31, wid = tid >> 5;
    int m0 = blockIdx.x * 128, n0 = blockIdx.y * 128;
    int kStart = blockIdx.z * kLen;
    out += (size_t)blockIdx.z * splitStride;
    int nch = kLen >> 5;

    // ---- loader (all 256 threads): 8 x 16B per chunk (16KB A + 16KB W)
    auto load_stage = [&](int stage, int c) {
        uint32_t sA = smem + stage * STAGE_BYTES;
        int k0 = kStart + (c << 5);
        const float* Ap = A + (size_t)m0 * lda + k0;
        const float* Wp = W + (size_t)n0 * ldw + k0;
#pragma unroll
        for (int i = 0; i < 4; i++) {
            int ch = tid + (i << 8);
            int row = ch >> 3, cc = ch & 7;
            uint32_t off = sw128((uint32_t)(row * 128 + cc * 16));
            cp16(sA + off,         Ap + (size_t)row * lda + cc * 4);
            cp16(sA + 16384 + off, Wp + (size_t)row * ldw + cc * 4);
        }
        cp_commit();
    };

    load_stage(0, 0);
    load_stage(1, 1);

    // ---- per-thread ldmatrix address invariants
    int wm = wid & 1, wn = wid >> 1;         // warp grid 2 (m) x 4 (n)
    int blk = lane >> 3, r8 = lane & 7;
    uint32_t xA[4], mAsk[4], xB[2], mBsk[2];
#pragma unroll
    for (int mt = 0; mt < 4; mt++) {
        int row = wm * 64 + mt * 16 + (blk & 1) * 8 + r8;
        xA[mt] = (uint32_t)(row * 128 + (blk >> 1) * 16);
        mAsk[mt] = (uint32_t)((row & 7) << 4);
    }
#pragma unroll
    for (int p = 0; p < 2; p++) {
        int row = wn * 32 + p * 16 + (blk >> 1) * 8 + r8;
        xB[p] = (uint32_t)(row * 128 + (blk & 1) * 16);
        mBsk[p] = (uint32_t)((row & 7) << 4);
    }

    float acc[4][4][4];
#pragma unroll
    for (int i = 0; i < 4; i++)
#pragma unroll
        for (int j = 0; j < 4; j++)
#pragma unroll
            for (int c = 0; c < 4; c++) acc[i][j][c] = 0.0f;

    // ---- main loop
    for (int c = 0; c < nch; c++) {
        asm volatile("cp.async.wait_group 1;" ::: "memory");
        __syncthreads();
        if (c + 2 < nch) load_stage((c + 2) % NSTAGE, c + 2);
        else cp_commit();  // keep wait_group counting consistent

        uint32_t sA = smem + (c % NSTAGE) * STAGE_BYTES;
        uint32_t sW = sA + 16384;
#pragma unroll
        for (int k8 = 0; k8 < 4; k8++) {
            uint32_t a[4][4], b[2][4];
#pragma unroll
            for (int mt = 0; mt < 4; mt++)
                ldsm4(a[mt], sA + ((xA[mt] + k8 * 32) ^ mAsk[mt]));
#pragma unroll
            for (int p = 0; p < 2; p++)
                ldsm4(b[p], sW + ((xB[p] + k8 * 32) ^ mBsk[p]));
#pragma unroll
            for (int mt = 0; mt < 4; mt++)
#pragma unroll
                for (int nt = 0; nt < 4; nt++)
                    mma168(acc[mt][nt], a[mt], b[nt >> 1][(nt & 1) * 2], b[nt >> 1][(nt & 1) * 2 + 1]);
        }
    }

    // ---- epilogue: direct gmem stores (+bias)
    int gid = lane >> 2, tig = lane & 3;
#pragma unroll
    for (int mt = 0; mt < 4; mt++) {
        int m = m0 + wm * 64 + mt * 16 + gid;
        float* o0 = out + (size_t)m * ldo + n0 + wn * 32;
        float* o1 = o0 + (size_t)8 * ldo;
#pragma unroll
        for (int nt = 0; nt < 4; nt++) {
            int nc = nt * 8 + 2 * tig;
            float bx = 0.0f, by = 0.0f;
            if (bias) {
                float2 bv = *(const float2*)(bias + n0 + wn * 32 + nc);
                bx = bv.x; by = bv.y;
            }
            float2 v0 = make_float2(acc[mt][nt][0] + bx, acc[mt][nt][1] + by);
            float2 v1 = make_float2(acc[mt][nt][2] + bx, acc[mt][nt][3] + by);
            *(float2*)(o0 + nc) = v0;
            *(float2*)(o1 + nc) = v1;
        }
    }
}

// ---------------- prep kernels ----------------
__global__ void prep_a(const float* __restrict__ x) {
    int t = blockIdx.y;
    int k = blockIdx.x * 256 + threadIdx.x;            // 16*256 = 4096 exact
    g_A[(size_t)t * KCAT + k] = tf32r(x[(size_t)t * DIN + k]);
}
__global__ void prep_w(const float* __restrict__ bw, const float* __restrict__ lB) {
    int n = blockIdx.y;
    int k = blockIdx.x * 256 + threadIdx.x;
    if (k >= KCAT) return;
    float v;
    if (k < DIN) v = bw[(size_t)n * DIN + k];
    else {
        int j = k - DIN, e = j >> 4, rr = j & 15;
        v = lB[((size_t)e * DOUT + n) * 16 + rr];
    }
    g_W[(size_t)n * KCAT + k] = tf32r(v);
}
__global__ void prep_la(const float* __restrict__ lA) {
    int row = blockIdx.y;                               // 0..127 (= e*16+r)
    int k = blockIdx.x * 256 + threadIdx.x;
    g_LA[(size_t)row * DIN + k] = tf32r(lA[(size_t)row * DIN + k]);
}
// gate: exact fp32 logits, top-2, softmax, coef = 2.0 * weight (scaling folded)
__global__ void gate_kernel(const float* __restrict__ x, const float* __restrict__ gw) {
    int t = blockIdx.x * 4 + (threadIdx.x >> 5);
    int lane = threadIdx.x & 31;
    const float4* xv = (const float4*)(x + (size_t)t * DIN);
    float acc[8] = {0,0,0,0,0,0,0,0};
    for (int i = lane; i < DIN/4; i += 32) {
        float4 xd = xv[i];
#pragma unroll
        for (int e = 0; e < 8; e++) {
            float4 wd = ((const float4*)(gw + (size_t)e * DIN))[i];
            acc[e] += xd.x*wd.x + xd.y*wd.y + xd.z*wd.z + xd.w*wd.w;
        }
    }
#pragma unroll
    for (int e = 0; e < 8; e++)
#pragma unroll
        for (int o = 16; o; o >>= 1) acc[e] += __shfl_xor_sync(~0u, acc[e], o);
    if (lane == 0) {
        int i1 = 0; float v1 = acc[0];
        for (int e = 1; e < 8; e++) if (acc[e] > v1) { v1 = acc[e]; i1 = e; }
        int i2 = -1; float v2 = -INFINITY;
        for (int e = 0; e < 8; e++) if (e != i1 && acc[e] > v2) { v2 = acc[e]; i2 = e; }
        float e2 = expf(v2 - v1);
        float inv = 1.0f / (1.0f + e2);
#pragma unroll
        for (int e = 0; e < 8; e++) g_coef[(size_t)t * 8 + e] = 0.0f;
        g_coef[(size_t)t * 8 + i1] = 2.0f * inv;
        g_coef[(size_t)t * 8 + i2] = 2.0f * e2 * inv;
    }
}
// ext: reduce split-K partials, scale by coef, write A ext columns
__global__ void ext_kernel() {
    int t = blockIdx.x, j = threadIdx.x;
    float s = 0.0f;
#pragma unroll
    for (int z = 0; z < NSPLIT; z++)
        s += g_lowp[((size_t)z * MTOT + t) * KEXT + j];
    float v = g_coef[(size_t)t * 8 + (j >> 4)] * s;
    g_A[(size_t)t * KCAT + DIN + j] = tf32r(v);
}

// ---------------- launch ----------------
extern "C" void kernel_launch(void* const* d_in, const int* in_sizes, int n_in,
                              void* d_out, int out_size) {
    const float* x      = (const float*)d_in[0];
    const float* gate_w = (const float*)d_in[1];
    const float* base_w = (const float*)d_in[2];
    const float* base_b = (const float*)d_in[3];
    const float* lora_A = (const float*)d_in[4];
    const float* lora_B = (const float*)d_in[5];
    float* out = (float*)d_out;

    cudaFuncSetAttribute(gemm_tf32, cudaFuncAttributeMaxDynamicSharedMemorySize, SMEM_SZ);

    float *pA, *pW, *pLA, *pLowp;
    cudaGetSymbolAddress((void**)&pA,    g_A);
    cudaGetSymbolAddress((void**)&pW,    g_W);
    cudaGetSymbolAddress((void**)&pLA,   g_LA);
    cudaGetSymbolAddress((void**)&pLowp, g_lowp);

    prep_a<<<dim3(16, MTOT), 256>>>(x);
    prep_w<<<dim3(17, DOUT), 256>>>(base_w, lora_B);
    prep_la<<<dim3(16, KEXT), 256>>>(lora_A);
    gate_kernel<<<MTOT/4, 128>>>(x, gate_w);
    // low partials = x @ lora_A^T, split-K over 8 slices of 512
    gemm_tf32<<<dim3(MTOT/128, 1, NSPLIT), 256, SMEM_SZ>>>(
        pA, KCAT, DIN/NSPLIT, pLA, DIN, pLowp, KEXT, nullptr, (long)MTOT * KEXT);
    ext_kernel<<<MTOT, KEXT>>>();
    // main: out = [x|ext] @ [base_w|lora_B]^T + bias
    gemm_tf32<<<dim3(MTOT/128, DOUT/128, 1), 256, SMEM_SZ>>>(
        pA, KCAT, KCAT, pW, KCAT, out, DOUT, base_b, 0);
}

// round 4
// speedup vs baseline: 1.0867x; 1.0867x over previous
#include <cuda_runtime.h>
#include <cstdint>
#include <math.h>

#define MTOT 4096
#define DIN  4096
#define DOUT 4096
#define KEXT 128
#define KCAT 4224          // DIN + KEXT
#define NSTAGE 3
#define STAGE_BYTES 32768  // 16KB A + 16KB W
#define SMEM_SZ (NSTAGE*STAGE_BYTES + 1024)
#define NSPLIT 8
#define GATE_SMEM (8*4096*4)

// ---------------- static device scratch ----------------
__device__ float g_A[(size_t)MTOT * KCAT];     // [x | ext], tf32-rounded
__device__ float g_W[(size_t)DOUT * KCAT];     // [base_w | lora_B flat], tf32-rounded
__device__ float g_LA[(size_t)KEXT * DIN];     // lora_A rows, tf32-rounded
__device__ float g_lowp[(size_t)NSPLIT * MTOT * KEXT]; // split-K partials of x @ lora_A^T
__device__ float g_coef[(size_t)MTOT * 8];     // scaling * routing weight (dense)

// ---------------- helpers ----------------
__device__ __forceinline__ uint32_t smem_u32(const void* p) {
    uint32_t a;
    asm("{ .reg .u64 t; cvta.to.shared.u64 t, %1; cvt.u32.u64 %0, t; }" : "=r"(a) : "l"(p));
    return a;
}
__device__ __forceinline__ uint32_t sw128(uint32_t o) { return o ^ ((o >> 3) & 0x70); }
__device__ __forceinline__ void cp16(uint32_t dst, const void* src) {
    asm volatile("cp.async.cg.shared.global [%0], [%1], 16;" :: "r"(dst), "l"(src) : "memory");
}
__device__ __forceinline__ void cp_commit() {
    asm volatile("cp.async.commit_group;" ::: "memory");
}
__device__ __forceinline__ float tf32r(float v) {
    uint32_t r; asm("cvt.rna.tf32.f32 %0, %1;" : "=r"(r) : "f"(v));
    return __uint_as_float(r);
}
__device__ __forceinline__ void ldsm4(uint32_t* r, uint32_t addr) {
    asm volatile("ldmatrix.sync.aligned.m8n8.x4.shared.b16 {%0,%1,%2,%3}, [%4];"
                 : "=r"(r[0]), "=r"(r[1]), "=r"(r[2]), "=r"(r[3]) : "r"(addr));
}
__device__ __forceinline__ void mma168(float* d, const uint32_t* a, uint32_t b0, uint32_t b1) {
    asm volatile("mma.sync.aligned.m16n8k8.row.col.f32.tf32.tf32.f32 "
                 "{%0,%1,%2,%3}, {%4,%5,%6,%7}, {%8,%9}, {%0,%1,%2,%3};"
                 : "+f"(d[0]), "+f"(d[1]), "+f"(d[2]), "+f"(d[3])
                 : "r"(a[0]), "r"(a[1]), "r"(a[2]), "r"(a[3]), "r"(b0), "r"(b1));
}

// ---------------- tf32 GEMM: out[M x N] = A[M x kLen] * W[N x kLen]^T (+bias) ----------------
// CTA tile 128x128, 256 threads (warp tile 64x32), K chunk 32, 3-stage cp.async pipeline.
// Split-K via blockIdx.z. CTA raster swizzled in supergroups of 8 M-blocks for L2 reuse.
__global__ void __launch_bounds__(256, 2) gemm_tf32(
    const float* __restrict__ A, int lda, int kLen,
    const float* __restrict__ W, int ldw,
    float* __restrict__ out, int ldo,
    const float* __restrict__ bias, long splitStride)
{
    extern __shared__ char dyn[];
    uint32_t smem = (smem_u32(dyn) + 1023u) & ~1023u;

    int tid = threadIdx.x, lane = tid & 31, wid = tid >> 5;

    // ---- CTA raster swizzle (supergroup of 8 M-blocks x all N-blocks)
    int mb = gridDim.x, nb = gridDim.y;
    int bid = blockIdx.y * mb + blockIdx.x;
    int G = mb < 8 ? mb : 8;
    int per = G * nb;
    int g = bid / per, r = bid % per;
    int gm = g * G;
    int h = (mb - gm) < G ? (mb - gm) : G;
    int m0 = (gm + r % h) * 128, n0 = (r / h) * 128;

    int kStart = blockIdx.z * kLen;
    out += (size_t)blockIdx.z * splitStride;
    int nch = kLen >> 5;

    // ---- loader (all 256 threads): 8 x 16B per chunk (16KB A + 16KB W)
    auto load_stage = [&](int stage, int c) {
        uint32_t sA = smem + stage * STAGE_BYTES;
        int k0 = kStart + (c << 5);
        const float* Ap = A + (size_t)m0 * lda + k0;
        const float* Wp = W + (size_t)n0 * ldw + k0;
#pragma unroll
        for (int i = 0; i < 4; i++) {
            int ch = tid + (i << 8);
            int row = ch >> 3, cc = ch & 7;
            uint32_t off = sw128((uint32_t)(row * 128 + cc * 16));
            cp16(sA + off,         Ap + (size_t)row * lda + cc * 4);
            cp16(sA + 16384 + off, Wp + (size_t)row * ldw + cc * 4);
        }
        cp_commit();
    };

    load_stage(0, 0);
    load_stage(1, 1);

    // ---- per-thread ldmatrix address invariants
    int wm = wid & 1, wn = wid >> 1;         // warp grid 2 (m) x 4 (n)
    int blk = lane >> 3, r8 = lane & 7;
    uint32_t xA[4], mAsk[4], xB[2], mBsk[2];
#pragma unroll
    for (int mt = 0; mt < 4; mt++) {
        int row = wm * 64 + mt * 16 + (blk & 1) * 8 + r8;
        xA[mt] = (uint32_t)(row * 128 + (blk >> 1) * 16);
        mAsk[mt] = (uint32_t)((row & 7) << 4);
    }
#pragma unroll
    for (int p = 0; p < 2; p++) {
        int row = wn * 32 + p * 16 + (blk >> 1) * 8 + r8;
        xB[p] = (uint32_t)(row * 128 + (blk & 1) * 16);
        mBsk[p] = (uint32_t)((row & 7) << 4);
    }

    float acc[4][4][4];
#pragma unroll
    for (int i = 0; i < 4; i++)
#pragma unroll
        for (int j = 0; j < 4; j++)
#pragma unroll
            for (int c = 0; c < 4; c++) acc[i][j][c] = 0.0f;

    // ---- main loop
    for (int c = 0; c < nch; c++) {
        asm volatile("cp.async.wait_group 1;" ::: "memory");
        __syncthreads();
        if (c + 2 < nch) load_stage((c + 2) % NSTAGE, c + 2);
        else cp_commit();  // keep wait_group counting consistent

        uint32_t sA = smem + (c % NSTAGE) * STAGE_BYTES;
        uint32_t sW = sA + 16384;
#pragma unroll
        for (int k8 = 0; k8 < 4; k8++) {
            uint32_t a[4][4], b[2][4];
#pragma unroll
            for (int mt = 0; mt < 4; mt++)
                ldsm4(a[mt], sA + ((xA[mt] + k8 * 32) ^ mAsk[mt]));
#pragma unroll
            for (int p = 0; p < 2; p++)
                ldsm4(b[p], sW + ((xB[p] + k8 * 32) ^ mBsk[p]));
#pragma unroll
            for (int mt = 0; mt < 4; mt++)
#pragma unroll
                for (int nt = 0; nt < 4; nt++)
                    mma168(acc[mt][nt], a[mt], b[nt >> 1][(nt & 1) * 2], b[nt >> 1][(nt & 1) * 2 + 1]);
        }
    }

    // ---- epilogue: direct gmem stores (+bias)
    int gid = lane >> 2, tig = lane & 3;
#pragma unroll
    for (int mt = 0; mt < 4; mt++) {
        int m = m0 + wm * 64 + mt * 16 + gid;
        float* o0 = out + (size_t)m * ldo + n0 + wn * 32;
        float* o1 = o0 + (size_t)8 * ldo;
#pragma unroll
        for (int nt = 0; nt < 4; nt++) {
            int nc = nt * 8 + 2 * tig;
            float bx = 0.0f, by = 0.0f;
            if (bias) {
                float2 bv = *(const float2*)(bias + n0 + wn * 32 + nc);
                bx = bv.x; by = bv.y;
            }
            *(float2*)(o0 + nc) = make_float2(acc[mt][nt][0] + bx, acc[mt][nt][1] + by);
            *(float2*)(o1 + nc) = make_float2(acc[mt][nt][2] + bx, acc[mt][nt][3] + by);
        }
    }
}

// ---------------- fused gate + A prep ----------------
// Block: 256 threads (8 warps x 4 tokens = 32 tokens), gate_w staged in 128KB smem.
// Computes exact fp32 logits -> top-2 softmax -> g_coef, and writes tf32(x) into g_A.
__global__ void __launch_bounds__(256) gate_prep(const float* __restrict__ x,
                                                 const float* __restrict__ gw) {
    extern __shared__ float sgw[];
    for (int i = threadIdx.x; i < 8 * 1024; i += 256)
        ((float4*)sgw)[i] = ((const float4*)gw)[i];
    __syncthreads();

    int warp = threadIdx.x >> 5, lane = threadIdx.x & 31;
    int t0 = blockIdx.x * 32 + warp * 4;

    float acc[4][8];
#pragma unroll
    for (int tt = 0; tt < 4; tt++)
#pragma unroll
        for (int e = 0; e < 8; e++) acc[tt][e] = 0.0f;

    for (int i = lane; i < 1024; i += 32) {
        float4 w4[8];
#pragma unroll
        for (int e = 0; e < 8; e++) w4[e] = ((const float4*)sgw)[e * 1024 + i];
#pragma unroll
        for (int tt = 0; tt < 4; tt++) {
            float4 xv = ((const float4*)(x + (size_t)(t0 + tt) * DIN))[i];
            float4 xr = make_float4(tf32r(xv.x), tf32r(xv.y), tf32r(xv.z), tf32r(xv.w));
            *(float4*)&g_A[(size_t)(t0 + tt) * KCAT + i * 4] = xr;
#pragma unroll
            for (int e = 0; e < 8; e++)
                acc[tt][e] += xv.x * w4[e].x + xv.y * w4[e].y + xv.z * w4[e].z + xv.w * w4[e].w;
        }
    }
#pragma unroll
    for (int tt = 0; tt < 4; tt++)
#pragma unroll
        for (int e = 0; e < 8; e++)
#pragma unroll
            for (int o = 16; o; o >>= 1)
                acc[tt][e] += __shfl_xor_sync(~0u, acc[tt][e], o);

    if (lane == 0) {
#pragma unroll
        for (int tt = 0; tt < 4; tt++) {
            int t = t0 + tt;
            float* a = acc[tt];
            int i1 = 0; float v1 = a[0];
            for (int e = 1; e < 8; e++) if (a[e] > v1) { v1 = a[e]; i1 = e; }
            int i2 = -1; float v2 = -INFINITY;
            for (int e = 0; e < 8; e++) if (e != i1 && a[e] > v2) { v2 = a[e]; i2 = e; }
            float e2 = expf(v2 - v1);
            float inv = 1.0f / (1.0f + e2);
#pragma unroll
            for (int e = 0; e < 8; e++) g_coef[(size_t)t * 8 + e] = 0.0f;
            g_coef[(size_t)t * 8 + i1] = 2.0f * inv;
            g_coef[(size_t)t * 8 + i2] = 2.0f * e2 * inv;
        }
    }
}

// ---------------- prep kernels (float4) ----------------
__global__ void __launch_bounds__(128) prep_w(const float* __restrict__ bw,
                                              const float* __restrict__ lB) {
    int n = blockIdx.y;
    int k4 = blockIdx.x * 128 + threadIdx.x;
    if (k4 >= KCAT / 4) return;
    float4 v;
    if (k4 < DIN / 4) {
        v = ((const float4*)(bw + (size_t)n * DIN))[k4];
    } else {
        int j4 = k4 - DIN / 4;                 // 0..31
        int e = j4 >> 2, rr4 = j4 & 3;
        v = *(const float4*)(lB + ((size_t)e * DOUT + n) * 16 + rr4 * 4);
    }
    v = make_float4(tf32r(v.x), tf32r(v.y), tf32r(v.z), tf32r(v.w));
    ((float4*)(g_W + (size_t)n * KCAT))[k4] = v;
}
__global__ void __launch_bounds__(128) prep_la(const float* __restrict__ lA) {
    int row = blockIdx.y;
    int k4 = blockIdx.x * 128 + threadIdx.x;
    float4 v = ((const float4*)(lA + (size_t)row * DIN))[k4];
    v = make_float4(tf32r(v.x), tf32r(v.y), tf32r(v.z), tf32r(v.w));
    ((float4*)(g_LA + (size_t)row * DIN))[k4] = v;
}
// ext: reduce split-K partials, scale by coef, write A ext columns
__global__ void __launch_bounds__(128) ext_kernel() {
    int t = blockIdx.x, j = threadIdx.x;
    float s = 0.0f;
#pragma unroll
    for (int z = 0; z < NSPLIT; z++)
        s += g_lowp[((size_t)z * MTOT + t) * KEXT + j];
    float v = g_coef[(size_t)t * 8 + (j >> 4)] * s;
    g_A[(size_t)t * KCAT + DIN + j] = tf32r(v);
}

// ---------------- launch ----------------
extern "C" void kernel_launch(void* const* d_in, const int* in_sizes, int n_in,
                              void* d_out, int out_size) {
    const float* x      = (const float*)d_in[0];
    const float* gate_w = (const float*)d_in[1];
    const float* base_w = (const float*)d_in[2];
    const float* base_b = (const float*)d_in[3];
    const float* lora_A = (const float*)d_in[4];
    const float* lora_B = (const float*)d_in[5];
    float* out = (float*)d_out;

    cudaFuncSetAttribute(gemm_tf32, cudaFuncAttributeMaxDynamicSharedMemorySize, SMEM_SZ);
    cudaFuncSetAttribute(gate_prep, cudaFuncAttributeMaxDynamicSharedMemorySize, GATE_SMEM);

    float *pA, *pW, *pLA, *pLowp;
    cudaGetSymbolAddress((void**)&pA,    g_A);
    cudaGetSymbolAddress((void**)&pW,    g_W);
    cudaGetSymbolAddress((void**)&pLA,   g_LA);
    cudaGetSymbolAddress((void**)&pLowp, g_lowp);

    gate_prep<<<MTOT / 32, 256, GATE_SMEM>>>(x, gate_w);            // g_A base + g_coef
    prep_la<<<dim3(8, KEXT), 128>>>(lora_A);
    prep_w<<<dim3((KCAT / 4 + 127) / 128, DOUT), 128>>>(base_w, lora_B);
    // low partials = x @ lora_A^T, split-K over 8 slices of 512
    gemm_tf32<<<dim3(MTOT / 128, 1, NSPLIT), 256, SMEM_SZ>>>(
        pA, KCAT, DIN / NSPLIT, pLA, DIN, pLowp, KEXT, nullptr, (long)MTOT * KEXT);
    ext_kernel<<<MTOT, KEXT>>>();
    // main: out = [x|ext] @ [base_w|lora_B]^T + bias
    gemm_tf32<<<dim3(MTOT / 128, DOUT / 128, 1), 256, SMEM_SZ>>>(
        pA, KCAT, KCAT, pW, KCAT, out, DOUT, base_b, 0);
}